// round 11
// baseline (speedup 1.0000x reference)
#include <cuda_runtime.h>
#include <cuda_bf16.h>
#include <cuda_fp8.h>
#include <cstdint>
#include <cstddef>

// ---------------- problem constants ----------------
#define BB 4
#define NN 2000
#define GG 20
#define ROWS (BB*NN)          // 8000
#define PADM 8064             // 63 * 128
#define FEAT 12544            // 256*7*7
#define HID 1024
#define NCLS 81
#define HEADN 256
#define THR 0.5f
#define NUM_POS 128
#define NUM_NEG 384
#define DENOM 2048.0f
#define W1_SCALE 64.0f
#define W1_INV (1.0f / 64.0f)

// ---------------- scratch (static device memory; no allocs) ----------------
// __device__ globals are zero-initialized; pad rows of g_Xq stay 0x00 == 0.0f.
__device__ uint8_t       g_Xq  [(size_t)PADM * FEAT];   // fp8 e4m3 X
__device__ uint8_t       g_W1q [(size_t)HID * FEAT];    // fp8 e4m3 W1^T * 64
__device__ __nv_bfloat16 g_W2t [(size_t)HID * HID];
__device__ __nv_bfloat16 g_Wcbt[(size_t)HEADN * HID];
__device__ float         g_bcb [HEADN];
__device__ __nv_bfloat16 g_h1b [(size_t)PADM * HID];
__device__ __nv_bfloat16 g_h2b [(size_t)PADM * HID];
__device__ float         g_logits[(size_t)PADM * HEADN];
__device__ int   g_label[ROWS];
__device__ float g_mbox[ROWS * 4];
__device__ int   g_samp[ROWS];
__device__ float g_loss[2];
__device__ unsigned g_done;

// ---------------- PTX helpers ----------------
__device__ __forceinline__ uint32_t s2u(const void* p) {
    uint32_t r;
    asm("{ .reg .u64 t; cvta.to.shared.u64 t, %1; cvt.u32.u64 %0, t; }"
        : "=r"(r) : "l"(p));
    return r;
}
__device__ __forceinline__ void cpa16(uint32_t dst, const void* src) {
    asm volatile("cp.async.cg.shared.global [%0], [%1], 16;" :: "r"(dst), "l"(src));
}
__device__ __forceinline__ void cpa_commit() {
    asm volatile("cp.async.commit_group;" ::: "memory");
}
template<int N>
__device__ __forceinline__ void cpa_wait() {
    asm volatile("cp.async.wait_group %0;" :: "n"(N) : "memory");
}
__device__ __forceinline__ void ldmx4(uint32_t* r, uint32_t addr) {
    asm volatile("ldmatrix.sync.aligned.m8n8.x4.shared.b16 {%0,%1,%2,%3}, [%4];"
        : "=r"(r[0]), "=r"(r[1]), "=r"(r[2]), "=r"(r[3]) : "r"(addr));
}
__device__ __forceinline__ void mma16816(float* c, const uint32_t* a, const uint32_t* b) {
    asm volatile(
        "mma.sync.aligned.m16n8k16.row.col.f32.bf16.bf16.f32 "
        "{%0,%1,%2,%3}, {%4,%5,%6,%7}, {%8,%9}, {%0,%1,%2,%3};"
        : "+f"(c[0]), "+f"(c[1]), "+f"(c[2]), "+f"(c[3])
        : "r"(a[0]), "r"(a[1]), "r"(a[2]), "r"(a[3]), "r"(b[0]), "r"(b[1]));
}
__device__ __forceinline__ void mma16832q(float* c, const uint32_t* a, uint32_t b0, uint32_t b1) {
    asm volatile(
        "mma.sync.aligned.m16n8k32.row.col.f32.e4m3.e4m3.f32 "
        "{%0,%1,%2,%3}, {%4,%5,%6,%7}, {%8,%9}, {%0,%1,%2,%3};"
        : "+f"(c[0]), "+f"(c[1]), "+f"(c[2]), "+f"(c[3])
        : "r"(a[0]), "r"(a[1]), "r"(a[2]), "r"(a[3]), "r"(b0), "r"(b1));
}

// ============ FP8 GEMM1: BM=128 BN=128 BK=128(bytes), 256 thr, 2 CTA/SM =====
// C[M,HID] = relu(X_fp8[M,K] @ (W1t_fp8*64)[HID,K]^T * (1/64) + bias), bf16 out
#define QSTAGES 3
#define QATILE 16384          // 128 rows x 128 B
#define QSTAGE_BYTES 32768
#define QGEMM_SMEM (QSTAGES * QSTAGE_BYTES)

__global__ __launch_bounds__(256, 2)
void gemm_fp8(const uint8_t* __restrict__ A, int lda,
              const uint8_t* __restrict__ Bw, int ldb,
              const float* __restrict__ bias,
              __nv_bfloat16* __restrict__ Cout, int ldc, int K)
{
    extern __shared__ __align__(1024) char dsmem[];
    const uint32_t tile0 = s2u(dsmem);

    const int tid = threadIdx.x;
    const int wid = tid >> 5;
    const int lid = tid & 31;
    const int warpM = wid >> 2;        // 0..1
    const int warpN = wid & 3;         // 0..3

    const int rowBase = blockIdx.y * 128;
    const int colBase = blockIdx.x * 128;
    const int CH = K >> 7;             // 128 fp8 elems per chunk

    #define QLOAD(c)                                                               \
    {                                                                              \
        const int slot_ = (c) % QSTAGES;                                           \
        const uint32_t aD_ = tile0 + slot_ * QSTAGE_BYTES;                         \
        const uint32_t bD_ = aD_ + QATILE;                                         \
        _Pragma("unroll")                                                          \
        for (int i_ = 0; i_ < 4; i_++) {                                           \
            int idx_ = tid + i_ * 256;                                             \
            int row_ = idx_ >> 3, c16_ = idx_ & 7;                                 \
            uint32_t off_ = row_ * 128 + (((c16_ ^ (row_ & 7)) << 4));             \
            cpa16(aD_ + off_, A  + (size_t)(rowBase + row_) * lda + (c) * 128 + c16_ * 16); \
            cpa16(bD_ + off_, Bw + (size_t)(colBase + row_) * ldb + (c) * 128 + c16_ * 16); \
        }                                                                          \
        cpa_commit();                                                              \
    }

    QLOAD(0);
    QLOAD(1);

    float acc[4][4][4];
    #pragma unroll
    for (int i = 0; i < 4; i++)
        #pragma unroll
        for (int j = 0; j < 4; j++)
            #pragma unroll
            for (int e = 0; e < 4; e++) acc[i][j][e] = 0.f;

    // lane->address maps (16B granules): identical geometry to the bf16 kernel;
    // for 8-bit mma each 16B chunk covers 16 k-values.
    const int aRowIn = (lid & 7) + ((lid & 8) ? 8 : 0);
    const int aC16add = (lid >> 4) & 1;
    const int bRowIn = (lid & 7) + ((lid >= 16) ? 8 : 0);
    const int bC16add = (lid >> 3) & 1;

    int aRow[4], bRow[2];
    #pragma unroll
    for (int i = 0; i < 4; i++) aRow[i] = warpM * 64 + i * 16 + aRowIn;
    #pragma unroll
    for (int j = 0; j < 2; j++) bRow[j] = warpN * 32 + j * 16 + bRowIn;

    for (int c = 0; c < CH; c++) {
        cpa_wait<QSTAGES - 2>();
        __syncthreads();
        if (c + QSTAGES - 1 < CH) {
            QLOAD(c + QSTAGES - 1);
        } else {
            cpa_commit();
        }

        const int slot = c % QSTAGES;
        const uint32_t aB = tile0 + slot * QSTAGE_BYTES;
        const uint32_t bB = aB + QATILE;

        #pragma unroll
        for (int ks = 0; ks < 4; ks++) {     // 4 x k32
            uint32_t aF[4][4], bF[2][4];
            #pragma unroll
            for (int i = 0; i < 4; i++) {
                int c16 = ks * 2 + aC16add;
                ldmx4(aF[i], aB + aRow[i] * 128 + (((c16 ^ (aRow[i] & 7)) << 4)));
            }
            #pragma unroll
            for (int j = 0; j < 2; j++) {
                int c16 = ks * 2 + bC16add;
                ldmx4(bF[j], bB + bRow[j] * 128 + (((c16 ^ (bRow[j] & 7)) << 4)));
            }
            #pragma unroll
            for (int i = 0; i < 4; i++)
                #pragma unroll
                for (int jj = 0; jj < 4; jj++)
                    mma16832q(acc[i][jj], aF[i],
                              bF[jj >> 1][(jj & 1) * 2], bF[jj >> 1][(jj & 1) * 2 + 1]);
        }
    }

    const int rq = lid >> 2;
    const int cq = (lid & 3) * 2;
    #pragma unroll
    for (int i = 0; i < 4; i++) {
        int m0 = rowBase + warpM * 64 + i * 16 + rq;
        #pragma unroll
        for (int j = 0; j < 4; j++) {
            int col = colBase + warpN * 32 + j * 8 + cq;
            float b0 = bias[col], b1 = bias[col + 1];
            float v00 = fmaxf(acc[i][j][0] * W1_INV + b0, 0.f);
            float v01 = fmaxf(acc[i][j][1] * W1_INV + b1, 0.f);
            float v10 = fmaxf(acc[i][j][2] * W1_INV + b0, 0.f);
            float v11 = fmaxf(acc[i][j][3] * W1_INV + b1, 0.f);
            *(__nv_bfloat162*)(Cout + (size_t)m0 * ldc + col)       = __floats2bfloat162_rn(v00, v01);
            *(__nv_bfloat162*)(Cout + (size_t)(m0 + 8) * ldc + col) = __floats2bfloat162_rn(v10, v11);
        }
    }
    #undef QLOAD
}

// ============ bf16 GEMM (R6-proven plain loop) ==============================
#define STAGES 3
#define ATILE 16384
#define STAGE_BYTES 32768
#define GEMM_SMEM (STAGES * STAGE_BYTES)

template<int RELU, int BF16OUT>
__global__ __launch_bounds__(256, 2)
void gemm_mma(const __nv_bfloat16* __restrict__ A, int lda,
              const __nv_bfloat16* __restrict__ Bw, int ldb,
              const float* __restrict__ bias,
              void* __restrict__ Cout, int ldc, int K)
{
    extern __shared__ __align__(1024) char dsmem[];
    const uint32_t tile0 = s2u(dsmem);

    const int tid = threadIdx.x;
    const int wid = tid >> 5;
    const int lid = tid & 31;
    const int warpM = wid >> 2;
    const int warpN = wid & 3;

    const int rowBase = blockIdx.y * 128;
    const int colBase = blockIdx.x * 128;
    const int CH = K >> 6;

    #define LOAD_STAGE(c)                                                          \
    {                                                                              \
        const int slot_ = (c) % STAGES;                                            \
        const uint32_t aD_ = tile0 + slot_ * STAGE_BYTES;                          \
        const uint32_t bD_ = aD_ + ATILE;                                          \
        _Pragma("unroll")                                                          \
        for (int i_ = 0; i_ < 4; i_++) {                                           \
            int idx_ = tid + i_ * 256;                                             \
            int row_ = idx_ >> 3, c16_ = idx_ & 7;                                 \
            uint32_t off_ = row_ * 128 + (((c16_ ^ (row_ & 7)) << 4));             \
            cpa16(aD_ + off_, A  + (size_t)(rowBase + row_) * lda + (c) * 64 + c16_ * 8); \
            cpa16(bD_ + off_, Bw + (size_t)(colBase + row_) * ldb + (c) * 64 + c16_ * 8); \
        }                                                                          \
        cpa_commit();                                                              \
    }

    LOAD_STAGE(0);
    LOAD_STAGE(1);

    float acc[4][4][4];
    #pragma unroll
    for (int i = 0; i < 4; i++)
        #pragma unroll
        for (int j = 0; j < 4; j++)
            #pragma unroll
            for (int e = 0; e < 4; e++) acc[i][j][e] = 0.f;

    const int aRowIn = (lid & 7) + ((lid & 8) ? 8 : 0);
    const int aC16add = (lid >> 4) & 1;
    const int bRowIn = (lid & 7) + ((lid >= 16) ? 8 : 0);
    const int bC16add = (lid >> 3) & 1;

    int aRow[4], bRow[2];
    #pragma unroll
    for (int i = 0; i < 4; i++) aRow[i] = warpM * 64 + i * 16 + aRowIn;
    #pragma unroll
    for (int j = 0; j < 2; j++) bRow[j] = warpN * 32 + j * 16 + bRowIn;

    for (int c = 0; c < CH; c++) {
        cpa_wait<STAGES - 2>();
        __syncthreads();
        if (c + STAGES - 1 < CH) {
            LOAD_STAGE(c + STAGES - 1);
        } else {
            cpa_commit();
        }

        const int slot = c % STAGES;
        const uint32_t aB = tile0 + slot * STAGE_BYTES;
        const uint32_t bB = aB + ATILE;

        #pragma unroll
        for (int ks = 0; ks < 4; ks++) {
            uint32_t aF[4][4], bF[2][4];
            #pragma unroll
            for (int i = 0; i < 4; i++) {
                int c16 = ks * 2 + aC16add;
                ldmx4(aF[i], aB + aRow[i] * 128 + (((c16 ^ (aRow[i] & 7)) << 4)));
            }
            #pragma unroll
            for (int j = 0; j < 2; j++) {
                int c16 = ks * 2 + bC16add;
                ldmx4(bF[j], bB + bRow[j] * 128 + (((c16 ^ (bRow[j] & 7)) << 4)));
            }
            #pragma unroll
            for (int i = 0; i < 4; i++)
                #pragma unroll
                for (int jj = 0; jj < 4; jj++)
                    mma16816(acc[i][jj], aF[i], &bF[jj >> 1][(jj & 1) * 2]);
        }
    }

    const int rq = lid >> 2;
    const int cq = (lid & 3) * 2;
    #pragma unroll
    for (int i = 0; i < 4; i++) {
        int m0 = rowBase + warpM * 64 + i * 16 + rq;
        #pragma unroll
        for (int j = 0; j < 4; j++) {
            int col = colBase + warpN * 32 + j * 8 + cq;
            float b0 = bias[col], b1 = bias[col + 1];
            float v00 = acc[i][j][0] + b0, v01 = acc[i][j][1] + b1;
            float v10 = acc[i][j][2] + b0, v11 = acc[i][j][3] + b1;
            if (RELU) {
                v00 = fmaxf(v00, 0.f); v01 = fmaxf(v01, 0.f);
                v10 = fmaxf(v10, 0.f); v11 = fmaxf(v11, 0.f);
            }
            if (BF16OUT) {
                __nv_bfloat16* O = (__nv_bfloat16*)Cout;
                *(__nv_bfloat162*)(O + (size_t)m0 * ldc + col)       = __floats2bfloat162_rn(v00, v01);
                *(__nv_bfloat162*)(O + (size_t)(m0 + 8) * ldc + col) = __floats2bfloat162_rn(v10, v11);
            } else {
                float* O = (float*)Cout;
                *(float2*)(O + (size_t)m0 * ldc + col)       = make_float2(v00, v01);
                *(float2*)(O + (size_t)(m0 + 8) * ldc + col) = make_float2(v10, v11);
            }
        }
    }
    #undef LOAD_STAGE
}

// ---------------- prep kernels ----------------
__device__ __forceinline__ uint8_t f2q(float v) {
    return (uint8_t)__nv_cvt_float_to_fp8(v, __NV_SATFINITE, __NV_E4M3);
}

__global__ void convert_X_fp8(const float* __restrict__ X) {
    // 16 floats -> 16 fp8 bytes per thread
    size_t i = (size_t)blockIdx.x * blockDim.x + threadIdx.x;
    size_t total = (size_t)ROWS * FEAT / 16;
    if (i >= total) return;
    size_t off = i * 16;
    uint32_t w[4];
    #pragma unroll
    for (int q = 0; q < 4; q++) {
        float4 v = *(const float4*)(X + off + q * 4);
        w[q] = (uint32_t)f2q(v.x) | ((uint32_t)f2q(v.y) << 8)
             | ((uint32_t)f2q(v.z) << 16) | ((uint32_t)f2q(v.w) << 24);
    }
    *(uint4*)(g_Xq + off) = make_uint4(w[0], w[1], w[2], w[3]);
}

// W1 [FEAT,HID] fp32 -> g_W1q [HID][FEAT] fp8 (x64)
__global__ void transpose_W1_fp8(const float* __restrict__ in) {
    __shared__ float t[32][33];
    int c0 = blockIdx.x * 32, r0 = blockIdx.y * 32;
    int tx = threadIdx.x, ty = threadIdx.y;
    for (int dy = 0; dy < 32; dy += 8)
        t[ty + dy][tx] = in[(size_t)(r0 + ty + dy) * HID + c0 + tx];
    __syncthreads();
    for (int dy = 0; dy < 32; dy += 8)
        g_W1q[(size_t)(c0 + ty + dy) * FEAT + r0 + tx] = f2q(t[tx][ty + dy] * W1_SCALE);
}

__global__ void transpose_bf16(const float* __restrict__ in, __nv_bfloat16* __restrict__ out,
                               int R, int C) {
    __shared__ float t[32][33];
    int c0 = blockIdx.x * 32, r0 = blockIdx.y * 32;
    int tx = threadIdx.x, ty = threadIdx.y;
    for (int dy = 0; dy < 32; dy += 8)
        t[ty + dy][tx] = in[(size_t)(r0 + ty + dy) * C + c0 + tx];
    __syncthreads();
    for (int dy = 0; dy < 32; dy += 8)
        out[(size_t)(c0 + ty + dy) * R + r0 + tx] = __float2bfloat16_rn(t[tx][ty + dy]);
}

__global__ void pack_head(const float* __restrict__ Wc, const float* __restrict__ bc,
                          const float* __restrict__ Wb, const float* __restrict__ bb) {
    int i = blockIdx.x * blockDim.x + threadIdx.x;
    if (i < HEADN * HID) {
        int n = i / HID, k = i % HID;
        float v = 0.f;
        if (n < NCLS) v = Wc[(size_t)k * NCLS + n];
        else if (n < NCLS + 4) v = Wb[(size_t)k * 4 + (n - NCLS)];
        g_Wcbt[i] = __float2bfloat16_rn(v);
    }
    if (i < HEADN) {
        float v = 0.f;
        if (i < NCLS) v = bc[i];
        else if (i < NCLS + 4) v = bb[i - NCLS];
        g_bcb[i] = v;
    }
}

// ---------------- labeling / sampling ----------------
__global__ void assign_kernel(const float* __restrict__ prop,
                              const float* __restrict__ gtb,
                              const int*   __restrict__ gtl) {
    int idx = blockIdx.x * blockDim.x + threadIdx.x;
    if (idx == 0) { g_loss[0] = 0.f; g_loss[1] = 0.f; g_done = 0u; }
    if (idx >= ROWS) return;
    int b = idx / NN;
    const float* p = prop + (size_t)idx * 4;
    float px1 = p[0], py1 = p[1], px2 = p[2], py2 = p[3];
    float ap = (px2 - px1) * (py2 - py1);
    float best = -1e30f; int bi = 0;
    for (int g = 0; g < GG; g++) {
        const float* gb = gtb + (size_t)(b * GG + g) * 4;
        float x1 = fmaxf(px1, gb[0]);
        float y1 = fmaxf(py1, gb[1]);
        float x2 = fminf(px2, gb[2]);
        float y2 = fminf(py2, gb[3]);
        float inter = fmaxf(x2 - x1, 0.f) * fmaxf(y2 - y1, 0.f);
        float ag = (gb[2] - gb[0]) * (gb[3] - gb[1]);
        float iou = inter / (ap + ag - inter);
        if (iou > best) { best = iou; bi = g; }
    }
    bool fg = best > THR;
    g_label[idx] = fg ? gtl[b * GG + bi] : 0;
    const float* gb = gtb + (size_t)(b * GG + bi) * 4;
    g_mbox[idx * 4 + 0] = fg ? gb[0] : 0.f;
    g_mbox[idx * 4 + 1] = fg ? gb[1] : 0.f;
    g_mbox[idx * 4 + 2] = fg ? gb[2] : 0.f;
    g_mbox[idx * 4 + 3] = fg ? gb[3] : 0.f;
}

__global__ __launch_bounds__(1024) void sample_kernel() {
    int b = blockIdx.x;
    __shared__ int sp[2048];
    __shared__ int sn[2048];
    int tid = threadIdx.x;
    int i0 = tid, i1 = tid + 1024;
    int l0 = (i0 < NN) ? g_label[b * NN + i0] : -1;
    int l1 = (i1 < NN) ? g_label[b * NN + i1] : -1;
    sp[i0] = (i0 < NN && l0 >= 1) ? 1 : 0;
    sn[i0] = (i0 < NN && l0 == 0) ? 1 : 0;
    sp[i1] = (i1 < NN && l1 >= 1) ? 1 : 0;
    sn[i1] = (i1 < NN && l1 == 0) ? 1 : 0;
    __syncthreads();
    for (int off = 1; off < 2048; off <<= 1) {
        int a0 = (i0 >= off) ? sp[i0 - off] : 0;
        int c0 = (i0 >= off) ? sn[i0 - off] : 0;
        int a1 = (i1 >= off) ? sp[i1 - off] : 0;
        int c1 = (i1 >= off) ? sn[i1 - off] : 0;
        __syncthreads();
        sp[i0] += a0; sn[i0] += c0; sp[i1] += a1; sn[i1] += c1;
        __syncthreads();
    }
    if (i0 < NN) {
        bool kp = (l0 >= 1) && (sp[i0] <= NUM_POS);
        bool kn = (l0 == 0) && (sn[i0] <= NUM_NEG);
        g_samp[b * NN + i0] = kp ? l0 : (kn ? 0 : -1);
    }
    if (i1 < NN) {
        bool kp = (l1 >= 1) && (sp[i1] <= NUM_POS);
        bool kn = (l1 == 0) && (sn[i1] <= NUM_NEG);
        g_samp[b * NN + i1] = kp ? l1 : (kn ? 0 : -1);
    }
}

// ---------------- per-row loss + fused finalize ----------------
#define LOSS_BLOCKS ((ROWS + 255) / 256)

__global__ void loss_kernel(const float* __restrict__ prop, float* __restrict__ out) {
    int r = blockIdx.x * blockDim.x + threadIdx.x;
    if (r < ROWS) {
        const float* lg = g_logits + (size_t)r * HEADN;

        float mx = -1e30f;
        for (int c = 0; c < NCLS; c++) mx = fmaxf(mx, lg[c]);
        float s = 0.f;
        float p[NCLS];
        for (int c = 0; c < NCLS; c++) { p[c] = expf(lg[c] - mx); s += p[c]; }
        float inv = 1.f / s;
        for (int c = 0; c < NCLS; c++) p[c] *= inv;
        float mx2 = -1e30f;
        for (int c = 0; c < NCLS; c++) mx2 = fmaxf(mx2, p[c]);
        float s2 = 0.f;
        for (int c = 0; c < NCLS; c++) s2 += expf(p[c] - mx2);
        float logZ = mx2 + logf(s2);

        int sv = g_samp[r];
        int tgt = sv > 0 ? sv : 0;
        float cls = (sv >= 0) ? (logZ - p[tgt]) : 0.f;

        float loc = 0.f;
        if (sv > 0) {
            const float* pb = prop + (size_t)r * 4;
            const float* gb = g_mbox + (size_t)r * 4;
            float pw  = pb[2] - pb[0];
            float ph  = pb[3] - pb[1];
            float pcx = pb[0] + 0.5f * pw;
            float pcy = pb[1] + 0.5f * ph;
            float gw  = gb[2] - gb[0];
            float gh  = gb[3] - gb[1];
            float gcx = 0.5f * (gb[0] + gb[2]);
            float gcy = 0.5f * (gb[1] + gb[3]);
            float gt_d[4];
            gt_d[0] = (gcx - pcx) / pw;
            gt_d[1] = (gcy - pcy) / ph;
            gt_d[2] = logf(gw / pw);
            gt_d[3] = logf(gh / ph);
            for (int c = 0; c < 4; c++) {
                float d  = lg[NCLS + c] - gt_d[c];
                float ad = fabsf(d);
                loc += (ad < 1.f) ? 0.5f * d * d : (ad - 0.5f);
            }
        }
        if (cls != 0.f) atomicAdd(&g_loss[0], cls);
        if (loc != 0.f) atomicAdd(&g_loss[1], loc);
    }
    __syncthreads();
    if (threadIdx.x == 0) {
        __threadfence();
        unsigned t = atomicAdd(&g_done, 1u);
        if (t == LOSS_BLOCKS - 1) {
            __threadfence();
            out[0] = g_loss[0] / DENOM;
            out[1] = g_loss[1] / DENOM;
        }
    }
}

// ---------------- launch -----------------------------------------------------
extern "C" void kernel_launch(void* const* d_in, const int* in_sizes, int n_in,
                              void* d_out, int out_size) {
    const float* X    = (const float*)d_in[0];
    const float* prop = (const float*)d_in[1];
    const float* gtb  = (const float*)d_in[2];
    const int*   gtl  = (const int*)  d_in[3];
    const float* W1   = (const float*)d_in[4];
    const float* b1   = (const float*)d_in[5];
    const float* W2   = (const float*)d_in[6];
    const float* b2   = (const float*)d_in[7];
    const float* Wc   = (const float*)d_in[8];
    const float* bc   = (const float*)d_in[9];
    const float* Wb   = (const float*)d_in[10];
    const float* bb   = (const float*)d_in[11];
    float* out = (float*)d_out;

    void *pXq, *pW1q, *pW2t, *pWcbt, *pbcb, *ph1, *ph2, *plg;
    cudaGetSymbolAddress(&pXq, g_Xq);
    cudaGetSymbolAddress(&pW1q, g_W1q);
    cudaGetSymbolAddress(&pW2t, g_W2t);
    cudaGetSymbolAddress(&pWcbt, g_Wcbt);
    cudaGetSymbolAddress(&pbcb, g_bcb);
    cudaGetSymbolAddress(&ph1, g_h1b);
    cudaGetSymbolAddress(&ph2, g_h2b);
    cudaGetSymbolAddress(&plg, g_logits);

    cudaFuncSetAttribute(gemm_fp8, cudaFuncAttributeMaxDynamicSharedMemorySize, QGEMM_SMEM);
    cudaFuncSetAttribute(gemm_mma<1, 1>, cudaFuncAttributeMaxDynamicSharedMemorySize, GEMM_SMEM);
    cudaFuncSetAttribute(gemm_mma<0, 0>, cudaFuncAttributeMaxDynamicSharedMemorySize, GEMM_SMEM);

    // launch index 3 == GEMM1 (fp8) so ncu profiles it
    {
        size_t tot = (size_t)ROWS * FEAT / 16;
        convert_X_fp8<<<(unsigned)((tot + 255) / 256), 256>>>(X);                 // 0
    }
    transpose_W1_fp8<<<dim3(HID / 32, FEAT / 32), dim3(32, 8)>>>(W1);             // 1
    transpose_bf16<<<dim3(HID / 32, HID / 32), dim3(32, 8)>>>(W2, (__nv_bfloat16*)pW2t, HID, HID); // 2

    gemm_fp8<<<dim3(HID / 128, PADM / 128), 256, QGEMM_SMEM>>>(                   // 3
        (const uint8_t*)pXq, FEAT, (const uint8_t*)pW1q, FEAT,
        b1, (__nv_bfloat16*)ph1, HID, FEAT);

    pack_head<<<(HEADN * HID + 255) / 256, 256>>>(Wc, bc, Wb, bb);                // 4

    gemm_mma<1, 1><<<dim3(HID / 128, PADM / 128), 256, GEMM_SMEM>>>(              // 5
        (const __nv_bfloat16*)ph1, HID, (const __nv_bfloat16*)pW2t, HID,
        b2, ph2, HID, HID);
    gemm_mma<0, 0><<<dim3(HEADN / 128, PADM / 128), 256, GEMM_SMEM>>>(            // 6
        (const __nv_bfloat16*)ph2, HID, (const __nv_bfloat16*)pWcbt, HID,
        (const float*)pbcb, plg, HEADN, HID);

    assign_kernel<<<(ROWS + 255) / 256, 256>>>(prop, gtb, gtl);                   // 7
    sample_kernel<<<BB, 1024>>>();                                                // 8
    loss_kernel<<<LOSS_BLOCKS, 256>>>(prop, out);                                 // 9
}

// round 12
// speedup vs baseline: 1.1207x; 1.1207x over previous
#include <cuda_runtime.h>
#include <cuda_bf16.h>
#include <cstdint>
#include <cstddef>

// ---------------- problem constants ----------------
#define BB 4
#define NN 2000
#define GG 20
#define ROWS (BB*NN)          // 8000
#define PADM 8064             // 63 * 128
#define FEAT 12544            // 256*7*7
#define HID 1024
#define NCLS 81
#define HEADN 256
#define THR 0.5f
#define NUM_POS 128
#define NUM_NEG 384
#define DENOM 2048.0f

// ---------------- scratch (static device memory; no allocs) ----------------
__device__ __nv_bfloat16 g_Xb  [(size_t)PADM * FEAT];
__device__ __nv_bfloat16 g_W1t [(size_t)HID * FEAT];
__device__ __nv_bfloat16 g_W2t [(size_t)HID * HID];
__device__ __nv_bfloat16 g_Wcbt[(size_t)HEADN * HID];
__device__ float         g_bcb [HEADN];
__device__ __nv_bfloat16 g_h1b [(size_t)PADM * HID];
__device__ __nv_bfloat16 g_h2b [(size_t)PADM * HID];
__device__ float         g_logits[(size_t)PADM * HEADN];
__device__ int   g_label[ROWS];
__device__ float g_mbox[ROWS * 4];
__device__ int   g_samp[ROWS];
__device__ float g_loss[2];
__device__ unsigned g_done;

// ---------------- PTX helpers (sm_80+ portable) ----------------
__device__ __forceinline__ uint32_t s2u(const void* p) {
    uint32_t r;
    asm("{ .reg .u64 t; cvta.to.shared.u64 t, %1; cvt.u32.u64 %0, t; }"
        : "=r"(r) : "l"(p));
    return r;
}
__device__ __forceinline__ void cpa16(uint32_t dst, const void* src) {
    asm volatile("cp.async.cg.shared.global [%0], [%1], 16;" :: "r"(dst), "l"(src));
}
__device__ __forceinline__ void cpa_commit() {
    asm volatile("cp.async.commit_group;" ::: "memory");
}
template<int N>
__device__ __forceinline__ void cpa_wait() {
    asm volatile("cp.async.wait_group %0;" :: "n"(N) : "memory");
}
__device__ __forceinline__ void ldmx4(uint32_t* r, uint32_t addr) {
    asm volatile("ldmatrix.sync.aligned.m8n8.x4.shared.b16 {%0,%1,%2,%3}, [%4];"
        : "=r"(r[0]), "=r"(r[1]), "=r"(r[2]), "=r"(r[3]) : "r"(addr));
}
__device__ __forceinline__ void mma16816(float* c, const uint32_t* a, const uint32_t* b) {
    asm volatile(
        "mma.sync.aligned.m16n8k16.row.col.f32.bf16.bf16.f32 "
        "{%0,%1,%2,%3}, {%4,%5,%6,%7}, {%8,%9}, {%0,%1,%2,%3};"
        : "+f"(c[0]), "+f"(c[1]), "+f"(c[2]), "+f"(c[3])
        : "r"(a[0]), "r"(a[1]), "r"(a[2]), "r"(a[3]), "r"(b[0]), "r"(b[1]));
}

// ============ bf16 mma.sync GEMM, BM=128 BN=128 BK=64, 256 thr, 2 CTA/SM ====
// Per-warp ks rotation staggers ldmatrix phases across warps so the tensor
// pipe stays fed while a subset of warps is in its shared-load phase.
#define STAGES 3
#define ATILE 16384
#define STAGE_BYTES 32768
#define GEMM_SMEM (STAGES * STAGE_BYTES)

template<int RELU, int BF16OUT>
__global__ __launch_bounds__(256, 2)
void gemm_mma(const __nv_bfloat16* __restrict__ A, int lda,
              const __nv_bfloat16* __restrict__ Bw, int ldb,
              const float* __restrict__ bias,
              void* __restrict__ Cout, int ldc, int K)
{
    extern __shared__ __align__(1024) char dsmem[];
    const uint32_t tile0 = s2u(dsmem);

    const int tid = threadIdx.x;
    const int wid = tid >> 5;
    const int lid = tid & 31;
    const int warpM = wid >> 2;        // 0..1
    const int warpN = wid & 3;         // 0..3
    const int rot = wid & 3;           // ks phase rotation per warp

    const int rowBase = blockIdx.y * 128;
    const int colBase = blockIdx.x * 128;
    const int CH = K >> 6;

    #define LOAD_STAGE(c)                                                          \
    {                                                                              \
        const int slot_ = (c) % STAGES;                                            \
        const uint32_t aD_ = tile0 + slot_ * STAGE_BYTES;                          \
        const uint32_t bD_ = aD_ + ATILE;                                          \
        _Pragma("unroll")                                                          \
        for (int i_ = 0; i_ < 4; i_++) {                                           \
            int idx_ = tid + i_ * 256;                                             \
            int row_ = idx_ >> 3, c16_ = idx_ & 7;                                 \
            uint32_t off_ = row_ * 128 + (((c16_ ^ (row_ & 7)) << 4));             \
            cpa16(aD_ + off_, A  + (size_t)(rowBase + row_) * lda + (c) * 64 + c16_ * 8); \
            cpa16(bD_ + off_, Bw + (size_t)(colBase + row_) * ldb + (c) * 64 + c16_ * 8); \
        }                                                                          \
        cpa_commit();                                                              \
    }

    LOAD_STAGE(0);
    LOAD_STAGE(1);

    float acc[4][4][4];
    #pragma unroll
    for (int i = 0; i < 4; i++)
        #pragma unroll
        for (int j = 0; j < 4; j++)
            #pragma unroll
            for (int e = 0; e < 4; e++) acc[i][j][e] = 0.f;

    const int aRowIn = (lid & 7) + ((lid & 8) ? 8 : 0);
    const int aC16add = (lid >> 4) & 1;
    const int bRowIn = (lid & 7) + ((lid >= 16) ? 8 : 0);
    const int bC16add = (lid >> 3) & 1;

    int aRow[4], bRow[2];
    #pragma unroll
    for (int i = 0; i < 4; i++) aRow[i] = warpM * 64 + i * 16 + aRowIn;
    #pragma unroll
    for (int j = 0; j < 2; j++) bRow[j] = warpN * 32 + j * 16 + bRowIn;

    for (int c = 0; c < CH; c++) {
        cpa_wait<STAGES - 2>();
        __syncthreads();
        if (c + STAGES - 1 < CH) {
            LOAD_STAGE(c + STAGES - 1);
        } else {
            cpa_commit();
        }

        const int slot = c % STAGES;
        const uint32_t aB = tile0 + slot * STAGE_BYTES;
        const uint32_t bB = aB + ATILE;

        #pragma unroll
        for (int ks0 = 0; ks0 < 4; ks0++) {
            const int ks = (ks0 + rot) & 3;     // staggered phase per warp
            uint32_t aF[4][4], bF[2][4];
            #pragma unroll
            for (int i = 0; i < 4; i++) {
                int c16 = ks * 2 + aC16add;
                ldmx4(aF[i], aB + aRow[i] * 128 + (((c16 ^ (aRow[i] & 7)) << 4)));
            }
            #pragma unroll
            for (int j = 0; j < 2; j++) {
                int c16 = ks * 2 + bC16add;
                ldmx4(bF[j], bB + bRow[j] * 128 + (((c16 ^ (bRow[j] & 7)) << 4)));
            }
            #pragma unroll
            for (int i = 0; i < 4; i++)
                #pragma unroll
                for (int jj = 0; jj < 4; jj++)
                    mma16816(acc[i][jj], aF[i], &bF[jj >> 1][(jj & 1) * 2]);
        }
    }

    // ---- epilogue ----
    const int rq = lid >> 2;
    const int cq = (lid & 3) * 2;
    #pragma unroll
    for (int i = 0; i < 4; i++) {
        int m0 = rowBase + warpM * 64 + i * 16 + rq;
        #pragma unroll
        for (int j = 0; j < 4; j++) {
            int col = colBase + warpN * 32 + j * 8 + cq;
            float b0 = bias[col], b1 = bias[col + 1];
            float v00 = acc[i][j][0] + b0, v01 = acc[i][j][1] + b1;
            float v10 = acc[i][j][2] + b0, v11 = acc[i][j][3] + b1;
            if (RELU) {
                v00 = fmaxf(v00, 0.f); v01 = fmaxf(v01, 0.f);
                v10 = fmaxf(v10, 0.f); v11 = fmaxf(v11, 0.f);
            }
            if (BF16OUT) {
                __nv_bfloat16* O = (__nv_bfloat16*)Cout;
                *(__nv_bfloat162*)(O + (size_t)m0 * ldc + col)       = __floats2bfloat162_rn(v00, v01);
                *(__nv_bfloat162*)(O + (size_t)(m0 + 8) * ldc + col) = __floats2bfloat162_rn(v10, v11);
            } else {
                float* O = (float*)Cout;
                *(float2*)(O + (size_t)m0 * ldc + col)       = make_float2(v00, v01);
                *(float2*)(O + (size_t)(m0 + 8) * ldc + col) = make_float2(v10, v11);
            }
        }
    }
    #undef LOAD_STAGE
}

// ---------------- prep kernels ----------------
__global__ void convert_X(const float* __restrict__ X) {
    size_t i = (size_t)blockIdx.x * blockDim.x + threadIdx.x;
    size_t total = (size_t)ROWS * FEAT / 8;
    if (i >= total) return;
    size_t off = i * 8;
    float4 v0 = *(const float4*)(X + off);
    float4 v1 = *(const float4*)(X + off + 4);
    uint4 pk;
    __nv_bfloat162 a = __floats2bfloat162_rn(v0.x, v0.y);
    __nv_bfloat162 b = __floats2bfloat162_rn(v0.z, v0.w);
    __nv_bfloat162 cc = __floats2bfloat162_rn(v1.x, v1.y);
    __nv_bfloat162 d = __floats2bfloat162_rn(v1.z, v1.w);
    pk.x = *(uint32_t*)&a; pk.y = *(uint32_t*)&b;
    pk.z = *(uint32_t*)&cc; pk.w = *(uint32_t*)&d;
    *(uint4*)(g_Xb + off) = pk;
}

__global__ void transpose_bf16(const float* __restrict__ in, __nv_bfloat16* __restrict__ out,
                               int R, int C) {
    __shared__ float t[32][33];
    int c0 = blockIdx.x * 32, r0 = blockIdx.y * 32;
    int tx = threadIdx.x, ty = threadIdx.y;
    for (int dy = 0; dy < 32; dy += 8)
        t[ty + dy][tx] = in[(size_t)(r0 + ty + dy) * C + c0 + tx];
    __syncthreads();
    for (int dy = 0; dy < 32; dy += 8)
        out[(size_t)(c0 + ty + dy) * R + r0 + tx] = __float2bfloat16_rn(t[tx][ty + dy]);
}

__global__ void pack_head(const float* __restrict__ Wc, const float* __restrict__ bc,
                          const float* __restrict__ Wb, const float* __restrict__ bb) {
    int i = blockIdx.x * blockDim.x + threadIdx.x;
    if (i < HEADN * HID) {
        int n = i / HID, k = i % HID;
        float v = 0.f;
        if (n < NCLS) v = Wc[(size_t)k * NCLS + n];
        else if (n < NCLS + 4) v = Wb[(size_t)k * 4 + (n - NCLS)];
        g_Wcbt[i] = __float2bfloat16_rn(v);
    }
    if (i < HEADN) {
        float v = 0.f;
        if (i < NCLS) v = bc[i];
        else if (i < NCLS + 4) v = bb[i - NCLS];
        g_bcb[i] = v;
    }
}

// ---------------- labeling / sampling ----------------
__global__ void assign_kernel(const float* __restrict__ prop,
                              const float* __restrict__ gtb,
                              const int*   __restrict__ gtl) {
    int idx = blockIdx.x * blockDim.x + threadIdx.x;
    if (idx == 0) { g_loss[0] = 0.f; g_loss[1] = 0.f; g_done = 0u; }
    if (idx >= ROWS) return;
    int b = idx / NN;
    const float* p = prop + (size_t)idx * 4;
    float px1 = p[0], py1 = p[1], px2 = p[2], py2 = p[3];
    float ap = (px2 - px1) * (py2 - py1);
    float best = -1e30f; int bi = 0;
    for (int g = 0; g < GG; g++) {
        const float* gb = gtb + (size_t)(b * GG + g) * 4;
        float x1 = fmaxf(px1, gb[0]);
        float y1 = fmaxf(py1, gb[1]);
        float x2 = fminf(px2, gb[2]);
        float y2 = fminf(py2, gb[3]);
        float inter = fmaxf(x2 - x1, 0.f) * fmaxf(y2 - y1, 0.f);
        float ag = (gb[2] - gb[0]) * (gb[3] - gb[1]);
        float iou = inter / (ap + ag - inter);
        if (iou > best) { best = iou; bi = g; }
    }
    bool fg = best > THR;
    g_label[idx] = fg ? gtl[b * GG + bi] : 0;
    const float* gb = gtb + (size_t)(b * GG + bi) * 4;
    g_mbox[idx * 4 + 0] = fg ? gb[0] : 0.f;
    g_mbox[idx * 4 + 1] = fg ? gb[1] : 0.f;
    g_mbox[idx * 4 + 2] = fg ? gb[2] : 0.f;
    g_mbox[idx * 4 + 3] = fg ? gb[3] : 0.f;
}

__global__ __launch_bounds__(1024) void sample_kernel() {
    int b = blockIdx.x;
    __shared__ int sp[2048];
    __shared__ int sn[2048];
    int tid = threadIdx.x;
    int i0 = tid, i1 = tid + 1024;
    int l0 = (i0 < NN) ? g_label[b * NN + i0] : -1;
    int l1 = (i1 < NN) ? g_label[b * NN + i1] : -1;
    sp[i0] = (i0 < NN && l0 >= 1) ? 1 : 0;
    sn[i0] = (i0 < NN && l0 == 0) ? 1 : 0;
    sp[i1] = (i1 < NN && l1 >= 1) ? 1 : 0;
    sn[i1] = (i1 < NN && l1 == 0) ? 1 : 0;
    __syncthreads();
    for (int off = 1; off < 2048; off <<= 1) {
        int a0 = (i0 >= off) ? sp[i0 - off] : 0;
        int c0 = (i0 >= off) ? sn[i0 - off] : 0;
        int a1 = (i1 >= off) ? sp[i1 - off] : 0;
        int c1 = (i1 >= off) ? sn[i1 - off] : 0;
        __syncthreads();
        sp[i0] += a0; sn[i0] += c0; sp[i1] += a1; sn[i1] += c1;
        __syncthreads();
    }
    if (i0 < NN) {
        bool kp = (l0 >= 1) && (sp[i0] <= NUM_POS);
        bool kn = (l0 == 0) && (sn[i0] <= NUM_NEG);
        g_samp[b * NN + i0] = kp ? l0 : (kn ? 0 : -1);
    }
    if (i1 < NN) {
        bool kp = (l1 >= 1) && (sp[i1] <= NUM_POS);
        bool kn = (l1 == 0) && (sn[i1] <= NUM_NEG);
        g_samp[b * NN + i1] = kp ? l1 : (kn ? 0 : -1);
    }
}

// ---------------- per-row loss + fused finalize ----------------
#define LOSS_BLOCKS ((ROWS + 255) / 256)

__global__ void loss_kernel(const float* __restrict__ prop, float* __restrict__ out) {
    int r = blockIdx.x * blockDim.x + threadIdx.x;
    if (r < ROWS) {
        const float* lg = g_logits + (size_t)r * HEADN;

        float mx = -1e30f;
        for (int c = 0; c < NCLS; c++) mx = fmaxf(mx, lg[c]);
        float s = 0.f;
        float p[NCLS];
        for (int c = 0; c < NCLS; c++) { p[c] = expf(lg[c] - mx); s += p[c]; }
        float inv = 1.f / s;
        for (int c = 0; c < NCLS; c++) p[c] *= inv;
        float mx2 = -1e30f;
        for (int c = 0; c < NCLS; c++) mx2 = fmaxf(mx2, p[c]);
        float s2 = 0.f;
        for (int c = 0; c < NCLS; c++) s2 += expf(p[c] - mx2);
        float logZ = mx2 + logf(s2);

        int sv = g_samp[r];
        int tgt = sv > 0 ? sv : 0;
        float cls = (sv >= 0) ? (logZ - p[tgt]) : 0.f;

        float loc = 0.f;
        if (sv > 0) {
            const float* pb = prop + (size_t)r * 4;
            const float* gb = g_mbox + (size_t)r * 4;
            float pw  = pb[2] - pb[0];
            float ph  = pb[3] - pb[1];
            float pcx = pb[0] + 0.5f * pw;
            float pcy = pb[1] + 0.5f * ph;
            float gw  = gb[2] - gb[0];
            float gh  = gb[3] - gb[1];
            float gcx = 0.5f * (gb[0] + gb[2]);
            float gcy = 0.5f * (gb[1] + gb[3]);
            float gt_d[4];
            gt_d[0] = (gcx - pcx) / pw;
            gt_d[1] = (gcy - pcy) / ph;
            gt_d[2] = logf(gw / pw);
            gt_d[3] = logf(gh / ph);
            for (int c = 0; c < 4; c++) {
                float d  = lg[NCLS + c] - gt_d[c];
                float ad = fabsf(d);
                loc += (ad < 1.f) ? 0.5f * d * d : (ad - 0.5f);
            }
        }
        if (cls != 0.f) atomicAdd(&g_loss[0], cls);
        if (loc != 0.f) atomicAdd(&g_loss[1], loc);
    }
    __syncthreads();
    if (threadIdx.x == 0) {
        __threadfence();
        unsigned t = atomicAdd(&g_done, 1u);
        if (t == LOSS_BLOCKS - 1) {
            __threadfence();
            out[0] = g_loss[0] / DENOM;
            out[1] = g_loss[1] / DENOM;
        }
    }
}

// ---------------- launch -----------------------------------------------------
extern "C" void kernel_launch(void* const* d_in, const int* in_sizes, int n_in,
                              void* d_out, int out_size) {
    const float* X    = (const float*)d_in[0];
    const float* prop = (const float*)d_in[1];
    const float* gtb  = (const float*)d_in[2];
    const int*   gtl  = (const int*)  d_in[3];
    const float* W1   = (const float*)d_in[4];
    const float* b1   = (const float*)d_in[5];
    const float* W2   = (const float*)d_in[6];
    const float* b2   = (const float*)d_in[7];
    const float* Wc   = (const float*)d_in[8];
    const float* bc   = (const float*)d_in[9];
    const float* Wb   = (const float*)d_in[10];
    const float* bb   = (const float*)d_in[11];
    float* out = (float*)d_out;

    void *pXb, *pW1t, *pW2t, *pWcbt, *pbcb, *ph1, *ph2, *plg;
    cudaGetSymbolAddress(&pXb, g_Xb);
    cudaGetSymbolAddress(&pW1t, g_W1t);
    cudaGetSymbolAddress(&pW2t, g_W2t);
    cudaGetSymbolAddress(&pWcbt, g_Wcbt);
    cudaGetSymbolAddress(&pbcb, g_bcb);
    cudaGetSymbolAddress(&ph1, g_h1b);
    cudaGetSymbolAddress(&ph2, g_h2b);
    cudaGetSymbolAddress(&plg, g_logits);

    cudaFuncSetAttribute(gemm_mma<1, 1>, cudaFuncAttributeMaxDynamicSharedMemorySize, GEMM_SMEM);
    cudaFuncSetAttribute(gemm_mma<0, 0>, cudaFuncAttributeMaxDynamicSharedMemorySize, GEMM_SMEM);

    // launch index 3 == GEMM1 so ncu profiles it
    {
        size_t tot = (size_t)ROWS * FEAT / 8;
        convert_X<<<(unsigned)((tot + 255) / 256), 256>>>(X);                     // 0
    }
    transpose_bf16<<<dim3(HID / 32, FEAT / 32), dim3(32, 8)>>>(W1, (__nv_bfloat16*)pW1t, FEAT, HID); // 1
    transpose_bf16<<<dim3(HID / 32, HID / 32), dim3(32, 8)>>>(W2, (__nv_bfloat16*)pW2t, HID, HID);   // 2

    gemm_mma<1, 1><<<dim3(HID / 128, PADM / 128), 256, GEMM_SMEM>>>(              // 3
        (const __nv_bfloat16*)pXb, FEAT, (const __nv_bfloat16*)pW1t, FEAT,
        b1, ph1, HID, FEAT);

    pack_head<<<(HEADN * HID + 255) / 256, 256>>>(Wc, bc, Wb, bb);                // 4

    gemm_mma<1, 1><<<dim3(HID / 128, PADM / 128), 256, GEMM_SMEM>>>(              // 5
        (const __nv_bfloat16*)ph1, HID, (const __nv_bfloat16*)pW2t, HID,
        b2, ph2, HID, HID);
    gemm_mma<0, 0><<<dim3(HEADN / 128, PADM / 128), 256, GEMM_SMEM>>>(            // 6
        (const __nv_bfloat16*)ph2, HID, (const __nv_bfloat16*)pWcbt, HID,
        (const float*)pbcb, plg, HEADN, HID);

    assign_kernel<<<(ROWS + 255) / 256, 256>>>(prop, gtb, gtl);                   // 7
    sample_kernel<<<BB, 1024>>>();                                                // 8
    loss_kernel<<<LOSS_BLOCKS, 256>>>(prop, out);                                 // 9
}

// round 13
// speedup vs baseline: 1.1233x; 1.0023x over previous
#include <cuda_runtime.h>
#include <cuda_bf16.h>
#include <cstdint>
#include <cstddef>

// ---------------- problem constants ----------------
#define BB 4
#define NN 2000
#define GG 20
#define ROWS (BB*NN)          // 8000
#define PADM 8064             // 63 * 128
#define FEAT 12544            // 256*7*7
#define HID 1024
#define NCLS 81
#define HEADN 256
#define THR 0.5f
#define NUM_POS 128
#define NUM_NEG 384
#define DENOM 2048.0f
#define H1ROWS 4096           // row split for GEMM1 halves (32 tiles / 31 tiles)

// ---------------- scratch (static device memory; no allocs) ----------------
__device__ __nv_bfloat16 g_Xb  [(size_t)PADM * FEAT];
__device__ __nv_bfloat16 g_W1t [(size_t)HID * FEAT];
__device__ __nv_bfloat16 g_W2t [(size_t)HID * HID];
__device__ __nv_bfloat16 g_Wcbt[(size_t)HEADN * HID];
__device__ float         g_bcb [HEADN];
__device__ __nv_bfloat16 g_h1b [(size_t)PADM * HID];
__device__ __nv_bfloat16 g_h2b [(size_t)PADM * HID];
__device__ float         g_logits[(size_t)PADM * HEADN];
__device__ int   g_label[ROWS];
__device__ float g_mbox[ROWS * 4];
__device__ int   g_samp[ROWS];
__device__ float g_loss[2];
__device__ unsigned g_done;

// ---------------- PTX helpers (sm_80+ portable) ----------------
__device__ __forceinline__ uint32_t s2u(const void* p) {
    uint32_t r;
    asm("{ .reg .u64 t; cvta.to.shared.u64 t, %1; cvt.u32.u64 %0, t; }"
        : "=r"(r) : "l"(p));
    return r;
}
__device__ __forceinline__ void cpa16(uint32_t dst, const void* src) {
    asm volatile("cp.async.cg.shared.global [%0], [%1], 16;" :: "r"(dst), "l"(src));
}
__device__ __forceinline__ void cpa_commit() {
    asm volatile("cp.async.commit_group;" ::: "memory");
}
template<int N>
__device__ __forceinline__ void cpa_wait() {
    asm volatile("cp.async.wait_group %0;" :: "n"(N) : "memory");
}
__device__ __forceinline__ void ldmx4(uint32_t* r, uint32_t addr) {
    asm volatile("ldmatrix.sync.aligned.m8n8.x4.shared.b16 {%0,%1,%2,%3}, [%4];"
        : "=r"(r[0]), "=r"(r[1]), "=r"(r[2]), "=r"(r[3]) : "r"(addr));
}
__device__ __forceinline__ void mma16816(float* c, const uint32_t* a, const uint32_t* b) {
    asm volatile(
        "mma.sync.aligned.m16n8k16.row.col.f32.bf16.bf16.f32 "
        "{%0,%1,%2,%3}, {%4,%5,%6,%7}, {%8,%9}, {%0,%1,%2,%3};"
        : "+f"(c[0]), "+f"(c[1]), "+f"(c[2]), "+f"(c[3])
        : "r"(a[0]), "r"(a[1]), "r"(a[2]), "r"(a[3]), "r"(b[0]), "r"(b[1]));
}

// ============ bf16 mma.sync GEMM (R11-proven: rotation, 256 thr, 2 CTA/SM) ==
#define STAGES 3
#define ATILE 16384
#define STAGE_BYTES 32768
#define GEMM_SMEM (STAGES * STAGE_BYTES)

template<int RELU, int BF16OUT>
__global__ __launch_bounds__(256, 2)
void gemm_mma(const __nv_bfloat16* __restrict__ A, int lda,
              const __nv_bfloat16* __restrict__ Bw, int ldb,
              const float* __restrict__ bias,
              void* __restrict__ Cout, int ldc, int K)
{
    extern __shared__ __align__(1024) char dsmem[];
    const uint32_t tile0 = s2u(dsmem);

    const int tid = threadIdx.x;
    const int wid = tid >> 5;
    const int lid = tid & 31;
    const int warpM = wid >> 2;
    const int warpN = wid & 3;
    const int rot = wid & 3;

    const int rowBase = blockIdx.y * 128;
    const int colBase = blockIdx.x * 128;
    const int CH = K >> 6;

    #define LOAD_STAGE(c)                                                          \
    {                                                                              \
        const int slot_ = (c) % STAGES;                                            \
        const uint32_t aD_ = tile0 + slot_ * STAGE_BYTES;                          \
        const uint32_t bD_ = aD_ + ATILE;                                          \
        _Pragma("unroll")                                                          \
        for (int i_ = 0; i_ < 4; i_++) {                                           \
            int idx_ = tid + i_ * 256;                                             \
            int row_ = idx_ >> 3, c16_ = idx_ & 7;                                 \
            uint32_t off_ = row_ * 128 + (((c16_ ^ (row_ & 7)) << 4));             \
            cpa16(aD_ + off_, A  + (size_t)(rowBase + row_) * lda + (c) * 64 + c16_ * 8); \
            cpa16(bD_ + off_, Bw + (size_t)(colBase + row_) * ldb + (c) * 64 + c16_ * 8); \
        }                                                                          \
        cpa_commit();                                                              \
    }

    LOAD_STAGE(0);
    LOAD_STAGE(1);

    float acc[4][4][4];
    #pragma unroll
    for (int i = 0; i < 4; i++)
        #pragma unroll
        for (int j = 0; j < 4; j++)
            #pragma unroll
            for (int e = 0; e < 4; e++) acc[i][j][e] = 0.f;

    const int aRowIn = (lid & 7) + ((lid & 8) ? 8 : 0);
    const int aC16add = (lid >> 4) & 1;
    const int bRowIn = (lid & 7) + ((lid >= 16) ? 8 : 0);
    const int bC16add = (lid >> 3) & 1;

    int aRow[4], bRow[2];
    #pragma unroll
    for (int i = 0; i < 4; i++) aRow[i] = warpM * 64 + i * 16 + aRowIn;
    #pragma unroll
    for (int j = 0; j < 2; j++) bRow[j] = warpN * 32 + j * 16 + bRowIn;

    for (int c = 0; c < CH; c++) {
        cpa_wait<STAGES - 2>();
        __syncthreads();
        if (c + STAGES - 1 < CH) {
            LOAD_STAGE(c + STAGES - 1);
        } else {
            cpa_commit();
        }

        const int slot = c % STAGES;
        const uint32_t aB = tile0 + slot * STAGE_BYTES;
        const uint32_t bB = aB + ATILE;

        #pragma unroll
        for (int ks0 = 0; ks0 < 4; ks0++) {
            const int ks = (ks0 + rot) & 3;
            uint32_t aF[4][4], bF[2][4];
            #pragma unroll
            for (int i = 0; i < 4; i++) {
                int c16 = ks * 2 + aC16add;
                ldmx4(aF[i], aB + aRow[i] * 128 + (((c16 ^ (aRow[i] & 7)) << 4)));
            }
            #pragma unroll
            for (int j = 0; j < 2; j++) {
                int c16 = ks * 2 + bC16add;
                ldmx4(bF[j], bB + bRow[j] * 128 + (((c16 ^ (bRow[j] & 7)) << 4)));
            }
            #pragma unroll
            for (int i = 0; i < 4; i++)
                #pragma unroll
                for (int jj = 0; jj < 4; jj++)
                    mma16816(acc[i][jj], aF[i], &bF[jj >> 1][(jj & 1) * 2]);
        }
    }

    const int rq = lid >> 2;
    const int cq = (lid & 3) * 2;
    #pragma unroll
    for (int i = 0; i < 4; i++) {
        int m0 = rowBase + warpM * 64 + i * 16 + rq;
        #pragma unroll
        for (int j = 0; j < 4; j++) {
            int col = colBase + warpN * 32 + j * 8 + cq;
            float b0 = bias[col], b1 = bias[col + 1];
            float v00 = acc[i][j][0] + b0, v01 = acc[i][j][1] + b1;
            float v10 = acc[i][j][2] + b0, v11 = acc[i][j][3] + b1;
            if (RELU) {
                v00 = fmaxf(v00, 0.f); v01 = fmaxf(v01, 0.f);
                v10 = fmaxf(v10, 0.f); v11 = fmaxf(v11, 0.f);
            }
            if (BF16OUT) {
                __nv_bfloat16* O = (__nv_bfloat16*)Cout;
                *(__nv_bfloat162*)(O + (size_t)m0 * ldc + col)       = __floats2bfloat162_rn(v00, v01);
                *(__nv_bfloat162*)(O + (size_t)(m0 + 8) * ldc + col) = __floats2bfloat162_rn(v10, v11);
            } else {
                float* O = (float*)Cout;
                *(float2*)(O + (size_t)m0 * ldc + col)       = make_float2(v00, v01);
                *(float2*)(O + (size_t)(m0 + 8) * ldc + col) = make_float2(v10, v11);
            }
        }
    }
    #undef LOAD_STAGE
}

// ---------------- prep kernels ----------------
// convert element range [e0, e0+n) (units of 8 floats per thread)
__global__ void convert_X(const float* __restrict__ X, size_t e0, size_t n8) {
    size_t i = (size_t)blockIdx.x * blockDim.x + threadIdx.x;
    if (i >= n8) return;
    size_t off = e0 + i * 8;
    float4 v0 = *(const float4*)(X + off);
    float4 v1 = *(const float4*)(X + off + 4);
    uint4 pk;
    __nv_bfloat162 a = __floats2bfloat162_rn(v0.x, v0.y);
    __nv_bfloat162 b = __floats2bfloat162_rn(v0.z, v0.w);
    __nv_bfloat162 cc = __floats2bfloat162_rn(v1.x, v1.y);
    __nv_bfloat162 d = __floats2bfloat162_rn(v1.z, v1.w);
    pk.x = *(uint32_t*)&a; pk.y = *(uint32_t*)&b;
    pk.z = *(uint32_t*)&cc; pk.w = *(uint32_t*)&d;
    *(uint4*)(g_Xb + off) = pk;
}

__global__ void transpose_bf16(const float* __restrict__ in, __nv_bfloat16* __restrict__ out,
                               int R, int C) {
    __shared__ float t[32][33];
    int c0 = blockIdx.x * 32, r0 = blockIdx.y * 32;
    int tx = threadIdx.x, ty = threadIdx.y;
    for (int dy = 0; dy < 32; dy += 8)
        t[ty + dy][tx] = in[(size_t)(r0 + ty + dy) * C + c0 + tx];
    __syncthreads();
    for (int dy = 0; dy < 32; dy += 8)
        out[(size_t)(c0 + ty + dy) * R + r0 + tx] = __float2bfloat16_rn(t[tx][ty + dy]);
}

__global__ void pack_head(const float* __restrict__ Wc, const float* __restrict__ bc,
                          const float* __restrict__ Wb, const float* __restrict__ bb) {
    int i = blockIdx.x * blockDim.x + threadIdx.x;
    if (i < HEADN * HID) {
        int n = i / HID, k = i % HID;
        float v = 0.f;
        if (n < NCLS) v = Wc[(size_t)k * NCLS + n];
        else if (n < NCLS + 4) v = Wb[(size_t)k * 4 + (n - NCLS)];
        g_Wcbt[i] = __float2bfloat16_rn(v);
    }
    if (i < HEADN) {
        float v = 0.f;
        if (i < NCLS) v = bc[i];
        else if (i < NCLS + 4) v = bb[i - NCLS];
        g_bcb[i] = v;
    }
}

// ---------------- labeling / sampling ----------------
__global__ void assign_kernel(const float* __restrict__ prop,
                              const float* __restrict__ gtb,
                              const int*   __restrict__ gtl) {
    int idx = blockIdx.x * blockDim.x + threadIdx.x;
    if (idx == 0) { g_loss[0] = 0.f; g_loss[1] = 0.f; g_done = 0u; }
    if (idx >= ROWS) return;
    int b = idx / NN;
    const float* p = prop + (size_t)idx * 4;
    float px1 = p[0], py1 = p[1], px2 = p[2], py2 = p[3];
    float ap = (px2 - px1) * (py2 - py1);
    float best = -1e30f; int bi = 0;
    for (int g = 0; g < GG; g++) {
        const float* gb = gtb + (size_t)(b * GG + g) * 4;
        float x1 = fmaxf(px1, gb[0]);
        float y1 = fmaxf(py1, gb[1]);
        float x2 = fminf(px2, gb[2]);
        float y2 = fminf(py2, gb[3]);
        float inter = fmaxf(x2 - x1, 0.f) * fmaxf(y2 - y1, 0.f);
        float ag = (gb[2] - gb[0]) * (gb[3] - gb[1]);
        float iou = inter / (ap + ag - inter);
        if (iou > best) { best = iou; bi = g; }
    }
    bool fg = best > THR;
    g_label[idx] = fg ? gtl[b * GG + bi] : 0;
    const float* gb = gtb + (size_t)(b * GG + bi) * 4;
    g_mbox[idx * 4 + 0] = fg ? gb[0] : 0.f;
    g_mbox[idx * 4 + 1] = fg ? gb[1] : 0.f;
    g_mbox[idx * 4 + 2] = fg ? gb[2] : 0.f;
    g_mbox[idx * 4 + 3] = fg ? gb[3] : 0.f;
}

__global__ __launch_bounds__(1024) void sample_kernel() {
    int b = blockIdx.x;
    __shared__ int sp[2048];
    __shared__ int sn[2048];
    int tid = threadIdx.x;
    int i0 = tid, i1 = tid + 1024;
    int l0 = (i0 < NN) ? g_label[b * NN + i0] : -1;
    int l1 = (i1 < NN) ? g_label[b * NN + i1] : -1;
    sp[i0] = (i0 < NN && l0 >= 1) ? 1 : 0;
    sn[i0] = (i0 < NN && l0 == 0) ? 1 : 0;
    sp[i1] = (i1 < NN && l1 >= 1) ? 1 : 0;
    sn[i1] = (i1 < NN && l1 == 0) ? 1 : 0;
    __syncthreads();
    for (int off = 1; off < 2048; off <<= 1) {
        int a0 = (i0 >= off) ? sp[i0 - off] : 0;
        int c0 = (i0 >= off) ? sn[i0 - off] : 0;
        int a1 = (i1 >= off) ? sp[i1 - off] : 0;
        int c1 = (i1 >= off) ? sn[i1 - off] : 0;
        __syncthreads();
        sp[i0] += a0; sn[i0] += c0; sp[i1] += a1; sn[i1] += c1;
        __syncthreads();
    }
    if (i0 < NN) {
        bool kp = (l0 >= 1) && (sp[i0] <= NUM_POS);
        bool kn = (l0 == 0) && (sn[i0] <= NUM_NEG);
        g_samp[b * NN + i0] = kp ? l0 : (kn ? 0 : -1);
    }
    if (i1 < NN) {
        bool kp = (l1 >= 1) && (sp[i1] <= NUM_POS);
        bool kn = (l1 == 0) && (sn[i1] <= NUM_NEG);
        g_samp[b * NN + i1] = kp ? l1 : (kn ? 0 : -1);
    }
}

// ---------------- per-row loss + fused finalize ----------------
#define LOSS_BLOCKS ((ROWS + 255) / 256)

__global__ void loss_kernel(const float* __restrict__ prop, float* __restrict__ out) {
    int r = blockIdx.x * blockDim.x + threadIdx.x;
    if (r < ROWS) {
        const float* lg = g_logits + (size_t)r * HEADN;

        float mx = -1e30f;
        for (int c = 0; c < NCLS; c++) mx = fmaxf(mx, lg[c]);
        float s = 0.f;
        float p[NCLS];
        for (int c = 0; c < NCLS; c++) { p[c] = expf(lg[c] - mx); s += p[c]; }
        float inv = 1.f / s;
        for (int c = 0; c < NCLS; c++) p[c] *= inv;
        float mx2 = -1e30f;
        for (int c = 0; c < NCLS; c++) mx2 = fmaxf(mx2, p[c]);
        float s2 = 0.f;
        for (int c = 0; c < NCLS; c++) s2 += expf(p[c] - mx2);
        float logZ = mx2 + logf(s2);

        int sv = g_samp[r];
        int tgt = sv > 0 ? sv : 0;
        float cls = (sv >= 0) ? (logZ - p[tgt]) : 0.f;

        float loc = 0.f;
        if (sv > 0) {
            const float* pb = prop + (size_t)r * 4;
            const float* gb = g_mbox + (size_t)r * 4;
            float pw  = pb[2] - pb[0];
            float ph  = pb[3] - pb[1];
            float pcx = pb[0] + 0.5f * pw;
            float pcy = pb[1] + 0.5f * ph;
            float gw  = gb[2] - gb[0];
            float gh  = gb[3] - gb[1];
            float gcx = 0.5f * (gb[0] + gb[2]);
            float gcy = 0.5f * (gb[1] + gb[3]);
            float gt_d[4];
            gt_d[0] = (gcx - pcx) / pw;
            gt_d[1] = (gcy - pcy) / ph;
            gt_d[2] = logf(gw / pw);
            gt_d[3] = logf(gh / ph);
            for (int c = 0; c < 4; c++) {
                float d  = lg[NCLS + c] - gt_d[c];
                float ad = fabsf(d);
                loc += (ad < 1.f) ? 0.5f * d * d : (ad - 0.5f);
            }
        }
        if (cls != 0.f) atomicAdd(&g_loss[0], cls);
        if (loc != 0.f) atomicAdd(&g_loss[1], loc);
    }
    __syncthreads();
    if (threadIdx.x == 0) {
        __threadfence();
        unsigned t = atomicAdd(&g_done, 1u);
        if (t == LOSS_BLOCKS - 1) {
            __threadfence();
            out[0] = g_loss[0] / DENOM;
            out[1] = g_loss[1] / DENOM;
        }
    }
}

// ---------------- launch: fork-join graph -----------------------------------
extern "C" void kernel_launch(void* const* d_in, const int* in_sizes, int n_in,
                              void* d_out, int out_size) {
    const float* X    = (const float*)d_in[0];
    const float* prop = (const float*)d_in[1];
    const float* gtb  = (const float*)d_in[2];
    const int*   gtl  = (const int*)  d_in[3];
    const float* W1   = (const float*)d_in[4];
    const float* b1   = (const float*)d_in[5];
    const float* W2   = (const float*)d_in[6];
    const float* b2   = (const float*)d_in[7];
    const float* Wc   = (const float*)d_in[8];
    const float* bc   = (const float*)d_in[9];
    const float* Wb   = (const float*)d_in[10];
    const float* bb   = (const float*)d_in[11];
    float* out = (float*)d_out;

    void *pXb, *pW1t, *pW2t, *pWcbt, *pbcb, *ph1, *ph2, *plg;
    cudaGetSymbolAddress(&pXb, g_Xb);
    cudaGetSymbolAddress(&pW1t, g_W1t);
    cudaGetSymbolAddress(&pW2t, g_W2t);
    cudaGetSymbolAddress(&pWcbt, g_Wcbt);
    cudaGetSymbolAddress(&pbcb, g_bcb);
    cudaGetSymbolAddress(&ph1, g_h1b);
    cudaGetSymbolAddress(&ph2, g_h2b);
    cudaGetSymbolAddress(&plg, g_logits);

    cudaFuncSetAttribute(gemm_mma<1, 1>, cudaFuncAttributeMaxDynamicSharedMemorySize, GEMM_SMEM);
    cudaFuncSetAttribute(gemm_mma<0, 0>, cudaFuncAttributeMaxDynamicSharedMemorySize, GEMM_SMEM);

    // Lazily create side stream + events ONCE (on the correctness call, before
    // graph capture). If creation fails, s1 stays 0 -> fully serial fallback.
    static cudaStream_t s1 = 0;
    static cudaEvent_t evFork = 0, evT = 0, evC = 0, evS = 0;
    static bool init_done = false;
    static bool use_fork = false;
    if (!init_done) {
        init_done = true;
        if (cudaStreamCreateWithFlags(&s1, cudaStreamNonBlocking) == cudaSuccess &&
            cudaEventCreateWithFlags(&evFork, cudaEventDisableTiming) == cudaSuccess &&
            cudaEventCreateWithFlags(&evT, cudaEventDisableTiming) == cudaSuccess &&
            cudaEventCreateWithFlags(&evC, cudaEventDisableTiming) == cudaSuccess &&
            cudaEventCreateWithFlags(&evS, cudaEventDisableTiming) == cudaSuccess) {
            use_fork = true;
        } else {
            s1 = 0;
        }
    }
    cudaStream_t sSide = use_fork ? s1 : 0;

    const __nv_bfloat16* Xb = (const __nv_bfloat16*)pXb;
    const __nv_bfloat16* W1t = (const __nv_bfloat16*)pW1t;
    __nv_bfloat16* h1 = (__nv_bfloat16*)ph1;

    // element ranges (units of 8 floats)
    const size_t e_half = (size_t)H1ROWS * FEAT;                 // rows [0,4096)
    const size_t n8_h1 = e_half / 8;
    const size_t n8_h2 = ((size_t)ROWS * FEAT - e_half) / 8;     // rows [4096,8000)

    if (use_fork) cudaEventRecord(evFork, 0);
    if (use_fork) cudaStreamWaitEvent(sSide, evFork, 0);

    // ---- side branch: W1 transpose (needed by GEMM1), conv half2, misc prep
    transpose_bf16<<<dim3(HID / 32, FEAT / 32), dim3(32, 8), 0, sSide>>>(
        W1, (__nv_bfloat16*)pW1t, FEAT, HID);
    if (use_fork) cudaEventRecord(evT, sSide);
    convert_X<<<(unsigned)((n8_h2 + 255) / 256), 256, 0, sSide>>>(X, e_half, n8_h2);
    if (use_fork) cudaEventRecord(evC, sSide);
    transpose_bf16<<<dim3(HID / 32, HID / 32), dim3(32, 8), 0, sSide>>>(
        W2, (__nv_bfloat16*)pW2t, HID, HID);
    pack_head<<<(HEADN * HID + 255) / 256, 256, 0, sSide>>>(Wc, bc, Wb, bb);
    assign_kernel<<<(ROWS + 255) / 256, 256, 0, sSide>>>(prop, gtb, gtl);
    sample_kernel<<<BB, 1024, 0, sSide>>>();
    if (use_fork) cudaEventRecord(evS, sSide);

    // ---- main branch
    convert_X<<<(unsigned)((n8_h1 + 255) / 256), 256>>>(X, 0, n8_h1);
    if (use_fork) cudaStreamWaitEvent(0, evT, 0);
    // GEMM1 half 1: rows [0, 4096)
    gemm_mma<1, 1><<<dim3(HID / 128, H1ROWS / 128), 256, GEMM_SMEM>>>(
        Xb, FEAT, W1t, FEAT, b1, h1, HID, FEAT);
    if (use_fork) cudaStreamWaitEvent(0, evC, 0);
    // GEMM1 half 2: rows [4096, 8064)
    gemm_mma<1, 1><<<dim3(HID / 128, (PADM - H1ROWS) / 128), 256, GEMM_SMEM>>>(
        Xb + (size_t)H1ROWS * FEAT, FEAT, W1t, FEAT, b1,
        h1 + (size_t)H1ROWS * HID, HID, FEAT);
    gemm_mma<1, 1><<<dim3(HID / 128, PADM / 128), 256, GEMM_SMEM>>>(
        (const __nv_bfloat16*)ph1, HID, (const __nv_bfloat16*)pW2t, HID,
        b2, ph2, HID, HID);
    gemm_mma<0, 0><<<dim3(HEADN / 128, PADM / 128), 256, GEMM_SMEM>>>(
        (const __nv_bfloat16*)ph2, HID, (const __nv_bfloat16*)pWcbt, HID,
        (const float*)pbcb, plg, HEADN, HID);
    if (use_fork) cudaStreamWaitEvent(0, evS, 0);
    loss_kernel<<<LOSS_BLOCKS, 256>>>(prop, out);
}

// round 14
// speedup vs baseline: 1.1798x; 1.0504x over previous
#include <cuda_runtime.h>
#include <cuda_bf16.h>
#include <cstdint>
#include <cstddef>

// ---------------- problem constants ----------------
#define BB 4
#define NN 2000
#define GG 20
#define ROWS (BB*NN)          // 8000
#define PADM 8064             // 63 * 128
#define FEAT 12544            // 256*7*7
#define HID 1024
#define NCLS 81
#define HEADN 256
#define THR 0.5f
#define NUM_POS 128
#define NUM_NEG 384
#define DENOM 2048.0f

// ---------------- scratch (static device memory; no allocs) ----------------
__device__ __nv_bfloat16 g_Xb  [(size_t)PADM * FEAT];
__device__ __nv_bfloat16 g_W1t [(size_t)HID * FEAT];
__device__ __nv_bfloat16 g_W2t [(size_t)HID * HID];
__device__ __nv_bfloat16 g_Wcbt[(size_t)HEADN * HID];
__device__ float         g_bcb [HEADN];
__device__ __nv_bfloat16 g_h1b [(size_t)PADM * HID];
__device__ __nv_bfloat16 g_h2b [(size_t)PADM * HID];
__device__ float         g_logits[(size_t)PADM * HEADN];
__device__ int   g_label[ROWS];
__device__ float g_mbox[ROWS * 4];
__device__ int   g_samp[ROWS];
__device__ float g_loss[2];
__device__ unsigned g_done;

// ---------------- PTX helpers (sm_80+ portable) ----------------
__device__ __forceinline__ uint32_t s2u(const void* p) {
    uint32_t r;
    asm("{ .reg .u64 t; cvta.to.shared.u64 t, %1; cvt.u32.u64 %0, t; }"
        : "=r"(r) : "l"(p));
    return r;
}
__device__ __forceinline__ void cpa16(uint32_t dst, const void* src) {
    asm volatile("cp.async.cg.shared.global [%0], [%1], 16;" :: "r"(dst), "l"(src));
}
__device__ __forceinline__ void cpa_commit() {
    asm volatile("cp.async.commit_group;" ::: "memory");
}
template<int N>
__device__ __forceinline__ void cpa_wait() {
    asm volatile("cp.async.wait_group %0;" :: "n"(N) : "memory");
}
__device__ __forceinline__ void ldmx4(uint32_t* r, uint32_t addr) {
    asm volatile("ldmatrix.sync.aligned.m8n8.x4.shared.b16 {%0,%1,%2,%3}, [%4];"
        : "=r"(r[0]), "=r"(r[1]), "=r"(r[2]), "=r"(r[3]) : "r"(addr));
}
__device__ __forceinline__ void mma16816(float* c, const uint32_t* a, const uint32_t* b) {
    asm volatile(
        "mma.sync.aligned.m16n8k16.row.col.f32.bf16.bf16.f32 "
        "{%0,%1,%2,%3}, {%4,%5,%6,%7}, {%8,%9}, {%0,%1,%2,%3};"
        : "+f"(c[0]), "+f"(c[1]), "+f"(c[2]), "+f"(c[3])
        : "r"(a[0]), "r"(a[1]), "r"(a[2]), "r"(a[3]), "r"(b[0]), "r"(b[1]));
}

// ==== bf16 mma.sync GEMM: BM=128 BN=128 BK=64, 128 thr (2x2 warps of 64x64) =
// 64x64 warp tile: 8 ldmatrix per ks feed 32 MMAs (ratio 1:4 vs 1:2.67 before).
#define STAGES 3
#define ATILE 16384
#define STAGE_BYTES 32768
#define GEMM_SMEM (STAGES * STAGE_BYTES)

template<int RELU, int BF16OUT>
__global__ __launch_bounds__(128, 2)
void gemm_mma(const __nv_bfloat16* __restrict__ A, int lda,
              const __nv_bfloat16* __restrict__ Bw, int ldb,
              const float* __restrict__ bias,
              void* __restrict__ Cout, int ldc, int K)
{
    extern __shared__ __align__(1024) char dsmem[];
    const uint32_t tile0 = s2u(dsmem);

    const int tid = threadIdx.x;
    const int wid = tid >> 5;          // 0..3
    const int lid = tid & 31;
    const int warpM = wid >> 1;        // 0..1  (64-row slab)
    const int warpN = wid & 1;         // 0..1  (64-col slab)
    const int rot = wid & 3;           // ks phase rotation

    const int rowBase = blockIdx.y * 128;
    const int colBase = blockIdx.x * 128;
    const int CH = K >> 6;

    #define LOAD_STAGE(c)                                                          \
    {                                                                              \
        const int slot_ = (c) % STAGES;                                            \
        const uint32_t aD_ = tile0 + slot_ * STAGE_BYTES;                          \
        const uint32_t bD_ = aD_ + ATILE;                                          \
        _Pragma("unroll")                                                          \
        for (int i_ = 0; i_ < 8; i_++) {                                           \
            int idx_ = tid + i_ * 128;                                             \
            int row_ = idx_ >> 3, c16_ = idx_ & 7;                                 \
            uint32_t off_ = row_ * 128 + (((c16_ ^ (row_ & 7)) << 4));             \
            cpa16(aD_ + off_, A  + (size_t)(rowBase + row_) * lda + (c) * 64 + c16_ * 8); \
            cpa16(bD_ + off_, Bw + (size_t)(colBase + row_) * ldb + (c) * 64 + c16_ * 8); \
        }                                                                          \
        cpa_commit();                                                              \
    }

    LOAD_STAGE(0);
    LOAD_STAGE(1);

    float acc[4][8][4];
    #pragma unroll
    for (int i = 0; i < 4; i++)
        #pragma unroll
        for (int j = 0; j < 8; j++)
            #pragma unroll
            for (int e = 0; e < 4; e++) acc[i][j][e] = 0.f;

    const int aRowIn = (lid & 7) + ((lid & 8) ? 8 : 0);
    const int aC16add = (lid >> 4) & 1;
    const int bRowIn = (lid & 7) + ((lid >= 16) ? 8 : 0);
    const int bC16add = (lid >> 3) & 1;

    int aRow[4], bRow[4];
    #pragma unroll
    for (int i = 0; i < 4; i++) aRow[i] = warpM * 64 + i * 16 + aRowIn;
    #pragma unroll
    for (int j = 0; j < 4; j++) bRow[j] = warpN * 64 + j * 16 + bRowIn;

    for (int c = 0; c < CH; c++) {
        cpa_wait<STAGES - 2>();
        __syncthreads();
        if (c + STAGES - 1 < CH) {
            LOAD_STAGE(c + STAGES - 1);
        } else {
            cpa_commit();
        }

        const int slot = c % STAGES;
        const uint32_t aB = tile0 + slot * STAGE_BYTES;
        const uint32_t bB = aB + ATILE;

        #pragma unroll
        for (int ks0 = 0; ks0 < 4; ks0++) {
            const int ks = (ks0 + rot) & 3;
            uint32_t aF[4][4], bF[4][4];
            #pragma unroll
            for (int i = 0; i < 4; i++) {
                int c16 = ks * 2 + aC16add;
                ldmx4(aF[i], aB + aRow[i] * 128 + (((c16 ^ (aRow[i] & 7)) << 4)));
            }
            #pragma unroll
            for (int j = 0; j < 4; j++) {
                int c16 = ks * 2 + bC16add;
                ldmx4(bF[j], bB + bRow[j] * 128 + (((c16 ^ (bRow[j] & 7)) << 4)));
            }
            #pragma unroll
            for (int i = 0; i < 4; i++)
                #pragma unroll
                for (int jj = 0; jj < 8; jj++)
                    mma16816(acc[i][jj], aF[i], &bF[jj >> 1][(jj & 1) * 2]);
        }
    }

    // ---- epilogue ----
    const int rq = lid >> 2;
    const int cq = (lid & 3) * 2;
    #pragma unroll
    for (int i = 0; i < 4; i++) {
        int m0 = rowBase + warpM * 64 + i * 16 + rq;
        #pragma unroll
        for (int j = 0; j < 8; j++) {
            int col = colBase + warpN * 64 + j * 8 + cq;
            float b0 = bias[col], b1 = bias[col + 1];
            float v00 = acc[i][j][0] + b0, v01 = acc[i][j][1] + b1;
            float v10 = acc[i][j][2] + b0, v11 = acc[i][j][3] + b1;
            if (RELU) {
                v00 = fmaxf(v00, 0.f); v01 = fmaxf(v01, 0.f);
                v10 = fmaxf(v10, 0.f); v11 = fmaxf(v11, 0.f);
            }
            if (BF16OUT) {
                __nv_bfloat16* O = (__nv_bfloat16*)Cout;
                *(__nv_bfloat162*)(O + (size_t)m0 * ldc + col)       = __floats2bfloat162_rn(v00, v01);
                *(__nv_bfloat162*)(O + (size_t)(m0 + 8) * ldc + col) = __floats2bfloat162_rn(v10, v11);
            } else {
                float* O = (float*)Cout;
                *(float2*)(O + (size_t)m0 * ldc + col)       = make_float2(v00, v01);
                *(float2*)(O + (size_t)(m0 + 8) * ldc + col) = make_float2(v10, v11);
            }
        }
    }
    #undef LOAD_STAGE
}

// ---------------- prep kernels ----------------
__global__ void convert_X(const float* __restrict__ X) {
    size_t i = (size_t)blockIdx.x * blockDim.x + threadIdx.x;
    size_t total = (size_t)ROWS * FEAT / 8;
    if (i >= total) return;
    size_t off = i * 8;
    float4 v0 = *(const float4*)(X + off);
    float4 v1 = *(const float4*)(X + off + 4);
    uint4 pk;
    __nv_bfloat162 a = __floats2bfloat162_rn(v0.x, v0.y);
    __nv_bfloat162 b = __floats2bfloat162_rn(v0.z, v0.w);
    __nv_bfloat162 cc = __floats2bfloat162_rn(v1.x, v1.y);
    __nv_bfloat162 d = __floats2bfloat162_rn(v1.z, v1.w);
    pk.x = *(uint32_t*)&a; pk.y = *(uint32_t*)&b;
    pk.z = *(uint32_t*)&cc; pk.w = *(uint32_t*)&d;
    *(uint4*)(g_Xb + off) = pk;
}

__global__ void transpose_bf16(const float* __restrict__ in, __nv_bfloat16* __restrict__ out,
                               int R, int C) {
    __shared__ float t[32][33];
    int c0 = blockIdx.x * 32, r0 = blockIdx.y * 32;
    int tx = threadIdx.x, ty = threadIdx.y;
    for (int dy = 0; dy < 32; dy += 8)
        t[ty + dy][tx] = in[(size_t)(r0 + ty + dy) * C + c0 + tx];
    __syncthreads();
    for (int dy = 0; dy < 32; dy += 8)
        out[(size_t)(c0 + ty + dy) * R + r0 + tx] = __float2bfloat16_rn(t[tx][ty + dy]);
}

__global__ void pack_head(const float* __restrict__ Wc, const float* __restrict__ bc,
                          const float* __restrict__ Wb, const float* __restrict__ bb) {
    int i = blockIdx.x * blockDim.x + threadIdx.x;
    if (i < HEADN * HID) {
        int n = i / HID, k = i % HID;
        float v = 0.f;
        if (n < NCLS) v = Wc[(size_t)k * NCLS + n];
        else if (n < NCLS + 4) v = Wb[(size_t)k * 4 + (n - NCLS)];
        g_Wcbt[i] = __float2bfloat16_rn(v);
    }
    if (i < HEADN) {
        float v = 0.f;
        if (i < NCLS) v = bc[i];
        else if (i < NCLS + 4) v = bb[i - NCLS];
        g_bcb[i] = v;
    }
}

// ---------------- labeling / sampling ----------------
__global__ void assign_kernel(const float* __restrict__ prop,
                              const float* __restrict__ gtb,
                              const int*   __restrict__ gtl) {
    int idx = blockIdx.x * blockDim.x + threadIdx.x;
    if (idx == 0) { g_loss[0] = 0.f; g_loss[1] = 0.f; g_done = 0u; }
    if (idx >= ROWS) return;
    int b = idx / NN;
    const float* p = prop + (size_t)idx * 4;
    float px1 = p[0], py1 = p[1], px2 = p[2], py2 = p[3];
    float ap = (px2 - px1) * (py2 - py1);
    float best = -1e30f; int bi = 0;
    for (int g = 0; g < GG; g++) {
        const float* gb = gtb + (size_t)(b * GG + g) * 4;
        float x1 = fmaxf(px1, gb[0]);
        float y1 = fmaxf(py1, gb[1]);
        float x2 = fminf(px2, gb[2]);
        float y2 = fminf(py2, gb[3]);
        float inter = fmaxf(x2 - x1, 0.f) * fmaxf(y2 - y1, 0.f);
        float ag = (gb[2] - gb[0]) * (gb[3] - gb[1]);
        float iou = inter / (ap + ag - inter);
        if (iou > best) { best = iou; bi = g; }
    }
    bool fg = best > THR;
    g_label[idx] = fg ? gtl[b * GG + bi] : 0;
    const float* gb = gtb + (size_t)(b * GG + bi) * 4;
    g_mbox[idx * 4 + 0] = fg ? gb[0] : 0.f;
    g_mbox[idx * 4 + 1] = fg ? gb[1] : 0.f;
    g_mbox[idx * 4 + 2] = fg ? gb[2] : 0.f;
    g_mbox[idx * 4 + 3] = fg ? gb[3] : 0.f;
}

__global__ __launch_bounds__(1024) void sample_kernel() {
    int b = blockIdx.x;
    __shared__ int sp[2048];
    __shared__ int sn[2048];
    int tid = threadIdx.x;
    int i0 = tid, i1 = tid + 1024;
    int l0 = (i0 < NN) ? g_label[b * NN + i0] : -1;
    int l1 = (i1 < NN) ? g_label[b * NN + i1] : -1;
    sp[i0] = (i0 < NN && l0 >= 1) ? 1 : 0;
    sn[i0] = (i0 < NN && l0 == 0) ? 1 : 0;
    sp[i1] = (i1 < NN && l1 >= 1) ? 1 : 0;
    sn[i1] = (i1 < NN && l1 == 0) ? 1 : 0;
    __syncthreads();
    for (int off = 1; off < 2048; off <<= 1) {
        int a0 = (i0 >= off) ? sp[i0 - off] : 0;
        int c0 = (i0 >= off) ? sn[i0 - off] : 0;
        int a1 = (i1 >= off) ? sp[i1 - off] : 0;
        int c1 = (i1 >= off) ? sn[i1 - off] : 0;
        __syncthreads();
        sp[i0] += a0; sn[i0] += c0; sp[i1] += a1; sn[i1] += c1;
        __syncthreads();
    }
    if (i0 < NN) {
        bool kp = (l0 >= 1) && (sp[i0] <= NUM_POS);
        bool kn = (l0 == 0) && (sn[i0] <= NUM_NEG);
        g_samp[b * NN + i0] = kp ? l0 : (kn ? 0 : -1);
    }
    if (i1 < NN) {
        bool kp = (l1 >= 1) && (sp[i1] <= NUM_POS);
        bool kn = (l1 == 0) && (sn[i1] <= NUM_NEG);
        g_samp[b * NN + i1] = kp ? l1 : (kn ? 0 : -1);
    }
}

// ---------------- per-row loss + fused finalize ----------------
#define LOSS_BLOCKS ((ROWS + 255) / 256)

__global__ void loss_kernel(const float* __restrict__ prop, float* __restrict__ out) {
    int r = blockIdx.x * blockDim.x + threadIdx.x;
    if (r < ROWS) {
        const float* lg = g_logits + (size_t)r * HEADN;

        float mx = -1e30f;
        for (int c = 0; c < NCLS; c++) mx = fmaxf(mx, lg[c]);
        float s = 0.f;
        float p[NCLS];
        for (int c = 0; c < NCLS; c++) { p[c] = expf(lg[c] - mx); s += p[c]; }
        float inv = 1.f / s;
        for (int c = 0; c < NCLS; c++) p[c] *= inv;
        float mx2 = -1e30f;
        for (int c = 0; c < NCLS; c++) mx2 = fmaxf(mx2, p[c]);
        float s2 = 0.f;
        for (int c = 0; c < NCLS; c++) s2 += expf(p[c] - mx2);
        float logZ = mx2 + logf(s2);

        int sv = g_samp[r];
        int tgt = sv > 0 ? sv : 0;
        float cls = (sv >= 0) ? (logZ - p[tgt]) : 0.f;

        float loc = 0.f;
        if (sv > 0) {
            const float* pb = prop + (size_t)r * 4;
            const float* gb = g_mbox + (size_t)r * 4;
            float pw  = pb[2] - pb[0];
            float ph  = pb[3] - pb[1];
            float pcx = pb[0] + 0.5f * pw;
            float pcy = pb[1] + 0.5f * ph;
            float gw  = gb[2] - gb[0];
            float gh  = gb[3] - gb[1];
            float gcx = 0.5f * (gb[0] + gb[2]);
            float gcy = 0.5f * (gb[1] + gb[3]);
            float gt_d[4];
            gt_d[0] = (gcx - pcx) / pw;
            gt_d[1] = (gcy - pcy) / ph;
            gt_d[2] = logf(gw / pw);
            gt_d[3] = logf(gh / ph);
            for (int c = 0; c < 4; c++) {
                float d  = lg[NCLS + c] - gt_d[c];
                float ad = fabsf(d);
                loc += (ad < 1.f) ? 0.5f * d * d : (ad - 0.5f);
            }
        }
        if (cls != 0.f) atomicAdd(&g_loss[0], cls);
        if (loc != 0.f) atomicAdd(&g_loss[1], loc);
    }
    __syncthreads();
    if (threadIdx.x == 0) {
        __threadfence();
        unsigned t = atomicAdd(&g_done, 1u);
        if (t == LOSS_BLOCKS - 1) {
            __threadfence();
            out[0] = g_loss[0] / DENOM;
            out[1] = g_loss[1] / DENOM;
        }
    }
}

// ---------------- launch: fork-join, GEMM1 unsplit ---------------------------
extern "C" void kernel_launch(void* const* d_in, const int* in_sizes, int n_in,
                              void* d_out, int out_size) {
    const float* X    = (const float*)d_in[0];
    const float* prop = (const float*)d_in[1];
    const float* gtb  = (const float*)d_in[2];
    const int*   gtl  = (const int*)  d_in[3];
    const float* W1   = (const float*)d_in[4];
    const float* b1   = (const float*)d_in[5];
    const float* W2   = (const float*)d_in[6];
    const float* b2   = (const float*)d_in[7];
    const float* Wc   = (const float*)d_in[8];
    const float* bc   = (const float*)d_in[9];
    const float* Wb   = (const float*)d_in[10];
    const float* bb   = (const float*)d_in[11];
    float* out = (float*)d_out;

    void *pXb, *pW1t, *pW2t, *pWcbt, *pbcb, *ph1, *ph2, *plg;
    cudaGetSymbolAddress(&pXb, g_Xb);
    cudaGetSymbolAddress(&pW1t, g_W1t);
    cudaGetSymbolAddress(&pW2t, g_W2t);
    cudaGetSymbolAddress(&pWcbt, g_Wcbt);
    cudaGetSymbolAddress(&pbcb, g_bcb);
    cudaGetSymbolAddress(&ph1, g_h1b);
    cudaGetSymbolAddress(&ph2, g_h2b);
    cudaGetSymbolAddress(&plg, g_logits);

    cudaFuncSetAttribute(gemm_mma<1, 1>, cudaFuncAttributeMaxDynamicSharedMemorySize, GEMM_SMEM);
    cudaFuncSetAttribute(gemm_mma<0, 0>, cudaFuncAttributeMaxDynamicSharedMemorySize, GEMM_SMEM);

    static cudaStream_t s1 = 0;
    static cudaEvent_t evFork = 0, evT = 0, evW2 = 0, evP = 0, evS = 0;
    static bool init_done = false;
    static bool use_fork = false;
    if (!init_done) {
        init_done = true;
        if (cudaStreamCreateWithFlags(&s1, cudaStreamNonBlocking) == cudaSuccess &&
            cudaEventCreateWithFlags(&evFork, cudaEventDisableTiming) == cudaSuccess &&
            cudaEventCreateWithFlags(&evT, cudaEventDisableTiming) == cudaSuccess &&
            cudaEventCreateWithFlags(&evW2, cudaEventDisableTiming) == cudaSuccess &&
            cudaEventCreateWithFlags(&evP, cudaEventDisableTiming) == cudaSuccess &&
            cudaEventCreateWithFlags(&evS, cudaEventDisableTiming) == cudaSuccess) {
            use_fork = true;
        } else {
            s1 = 0;
        }
    }
    cudaStream_t sSide = use_fork ? s1 : 0;

    if (use_fork) { cudaEventRecord(evFork, 0); cudaStreamWaitEvent(sSide, evFork, 0); }

    // submission 0: conv_X (main)
    {
        size_t tot = (size_t)ROWS * FEAT / 8;
        convert_X<<<(unsigned)((tot + 255) / 256), 256>>>(X);
    }
    // submission 1: W1 transpose (side) -> evT
    transpose_bf16<<<dim3(HID / 32, FEAT / 32), dim3(32, 8), 0, sSide>>>(
        W1, (__nv_bfloat16*)pW1t, FEAT, HID);
    if (use_fork) cudaEventRecord(evT, sSide);
    // submission 2: W2 transpose (side) -> evW2
    transpose_bf16<<<dim3(HID / 32, HID / 32), dim3(32, 8), 0, sSide>>>(
        W2, (__nv_bfloat16*)pW2t, HID, HID);
    if (use_fork) cudaEventRecord(evW2, sSide);
    // submission 3: GEMM1 (main; after conv + evT)  <- ncu profiles this
    if (use_fork) cudaStreamWaitEvent(0, evT, 0);
    gemm_mma<1, 1><<<dim3(HID / 128, PADM / 128), 128, GEMM_SMEM>>>(
        (const __nv_bfloat16*)pXb, FEAT, (const __nv_bfloat16*)pW1t, FEAT,
        b1, ph1, HID, FEAT);
    // submissions 4-6: pack/assign/sample (side) -> evP, evS
    pack_head<<<(HEADN * HID + 255) / 256, 256, 0, sSide>>>(Wc, bc, Wb, bb);
    if (use_fork) cudaEventRecord(evP, sSide);
    assign_kernel<<<(ROWS + 255) / 256, 256, 0, sSide>>>(prop, gtb, gtl);
    sample_kernel<<<BB, 1024, 0, sSide>>>();
    if (use_fork) cudaEventRecord(evS, sSide);
    // submission 7: GEMM2 (main; after evW2)
    if (use_fork) cudaStreamWaitEvent(0, evW2, 0);
    gemm_mma<1, 1><<<dim3(HID / 128, PADM / 128), 128, GEMM_SMEM>>>(
        (const __nv_bfloat16*)ph1, HID, (const __nv_bfloat16*)pW2t, HID,
        b2, ph2, HID, HID);
    // submission 8: head (main; after evP)
    if (use_fork) cudaStreamWaitEvent(0, evP, 0);
    gemm_mma<0, 0><<<dim3(HEADN / 128, PADM / 128), 128, GEMM_SMEM>>>(
        (const __nv_bfloat16*)ph2, HID, (const __nv_bfloat16*)pWcbt, HID,
        (const float*)pbcb, plg, HEADN, HID);
    // submission 9: loss (main; after evS)
    if (use_fork) cudaStreamWaitEvent(0, evS, 0);
    loss_kernel<<<LOSS_BLOCKS, 256>>>(prop, out);
}